// round 1
// baseline (speedup 1.0000x reference)
#include <cuda_runtime.h>
#include <math.h>

// Problem constants
// B=8, N=1024, C=768, H=12, DH=64, SCALE = 1/8
#define NB 8
#define NSEQ 1024
#define NC 768
#define NH 12
#define NDH 64
#define SCALE 0.125f

// Scratch (device globals; allocation inside kernel_launch is forbidden)
__device__ float g_qh[NB * NH * NSEQ * NDH];     // [B,H,N,64]
__device__ float g_kh[NB * NH * NSEQ * NDH];
__device__ float g_vh[NB * NH * NSEQ * NDH];
__device__ float g_fattn[NB * NH * NDH * NDH];   // [B,H,64,64]
__device__ float g_tmp[NB * NSEQ * NC];          // t + f, [B,N,C]

// ---------------------------------------------------------------------------
// Kernel 1: fused QKV projection GEMM.
//   cols [0,768)    : q @ Wq      -> g_qh  (head-major scatter)
//   cols [768,2304) : k @ Wkv     -> g_kh / g_vh
// 128x128x8 register-tiled SGEMM, 256 threads, 8x8 per thread.
// ---------------------------------------------------------------------------
__global__ __launch_bounds__(256) void qkv_gemm(const float* __restrict__ q,
                                                const float* __restrict__ kx,
                                                const float* __restrict__ Wq,
                                                const float* __restrict__ Wkv) {
    __shared__ __align__(16) float As[8 * 132];
    __shared__ __align__(16) float Bs[8 * 128];
    const int n0 = blockIdx.x * 128;
    const int m0 = blockIdx.y * 128;
    const bool isQ = (n0 < 768);
    const float* A;
    const float* Bm;
    int ldb, cbase;
    if (isQ) { A = q;  Bm = Wq;  ldb = 768;  cbase = n0; }
    else     { A = kx; Bm = Wkv; ldb = 1536; cbase = n0 - 768; }

    const int t  = threadIdx.x;
    const int tx = t & 15, ty = t >> 4;
    const int am = t >> 1,  ak = (t & 1) * 4;
    const int bk = t >> 5,  bn = (t & 31) * 4;

    float acc[8][8] = {};
    for (int k0 = 0; k0 < 768; k0 += 8) {
        float4 av = *(const float4*)(A  + (size_t)(m0 + am) * 768 + k0 + ak);
        float4 bv = *(const float4*)(Bm + (size_t)(k0 + bk) * ldb + cbase + bn);
        __syncthreads();
        As[(ak + 0) * 132 + am] = av.x;
        As[(ak + 1) * 132 + am] = av.y;
        As[(ak + 2) * 132 + am] = av.z;
        As[(ak + 3) * 132 + am] = av.w;
        *(float4*)&Bs[bk * 128 + bn] = bv;
        __syncthreads();
#pragma unroll
        for (int kk = 0; kk < 8; kk++) {
            float a[8], b[8];
            *(float4*)&a[0] = *(const float4*)&As[kk * 132 + ty * 8];
            *(float4*)&a[4] = *(const float4*)&As[kk * 132 + ty * 8 + 4];
            *(float4*)&b[0] = *(const float4*)&Bs[kk * 128 + tx * 8];
            *(float4*)&b[4] = *(const float4*)&Bs[kk * 128 + tx * 8 + 4];
#pragma unroll
            for (int i = 0; i < 8; i++)
#pragma unroll
                for (int j = 0; j < 8; j++)
                    acc[i][j] += a[i] * b[j];
        }
    }

#pragma unroll
    for (int i = 0; i < 8; i++) {
        const int m  = m0 + ty * 8 + i;
        const int bb = m >> 10;      // batch
        const int n  = m & 1023;     // token
#pragma unroll
        for (int j = 0; j < 8; j++) {
            const int c = cbase + tx * 8 + j;
            const float v = acc[i][j];
            if (isQ) {
                const int h = c >> 6, d = c & 63;
                g_qh[(((size_t)bb * NH + h) * NSEQ + n) * NDH + d] = v;
            } else {
                const int cc = (c >= 768) ? (c - 768) : c;
                const int h = cc >> 6, d = cc & 63;
                float* dst = (c >= 768) ? g_vh : g_kh;
                dst[(((size_t)bb * NH + h) * NSEQ + n) * NDH + d] = v;
            }
        }
    }
}

// ---------------------------------------------------------------------------
// Kernel 2: feature attention  f_attn[b,h,d,e] = softmax_e( (qh^T kh)[d,e] * SCALE )
// One block per (b,h). S is 64x64, contraction over N=1024.
// Thread (ty,tx): rows d = ty*4..+3, cols e = tx*4..+3.
// ---------------------------------------------------------------------------
__global__ __launch_bounds__(256) void fattn_kernel() {
    const int bh = blockIdx.x;
    const float* Q = g_qh + (size_t)bh * NSEQ * NDH;
    const float* K = g_kh + (size_t)bh * NSEQ * NDH;
    __shared__ __align__(16) float Qt[32 * 65];
    __shared__ __align__(16) float Kt[32 * 65];
    const int t = threadIdx.x, tx = t & 15, ty = t >> 4;

    float acc[4][4] = {};
    for (int n0 = 0; n0 < NSEQ; n0 += 32) {
        __syncthreads();
#pragma unroll
        for (int u = 0; u < 2; u++) {
            const int f4 = t + u * 256;
            const int row = f4 >> 4, col = (f4 & 15) * 4;
            float4 qv = *(const float4*)(Q + (size_t)(n0 + row) * 64 + col);
            float4 kv = *(const float4*)(K + (size_t)(n0 + row) * 64 + col);
            Qt[row * 65 + col + 0] = qv.x; Qt[row * 65 + col + 1] = qv.y;
            Qt[row * 65 + col + 2] = qv.z; Qt[row * 65 + col + 3] = qv.w;
            Kt[row * 65 + col + 0] = kv.x; Kt[row * 65 + col + 1] = kv.y;
            Kt[row * 65 + col + 2] = kv.z; Kt[row * 65 + col + 3] = kv.w;
        }
        __syncthreads();
#pragma unroll 8
        for (int nn = 0; nn < 32; nn++) {
            float a[4], b[4];
#pragma unroll
            for (int i = 0; i < 4; i++) a[i] = Qt[nn * 65 + ty * 4 + i];
#pragma unroll
            for (int j = 0; j < 4; j++) b[j] = Kt[nn * 65 + tx * 4 + j];
#pragma unroll
            for (int i = 0; i < 4; i++)
#pragma unroll
                for (int j = 0; j < 4; j++)
                    acc[i][j] += a[i] * b[j];
        }
    }

    float* outp = g_fattn + (size_t)bh * 4096;
#pragma unroll
    for (int i = 0; i < 4; i++) {
        float s[4];
        float mx = -INFINITY;
#pragma unroll
        for (int j = 0; j < 4; j++) { s[j] = acc[i][j] * SCALE; mx = fmaxf(mx, s[j]); }
        for (int o = 8; o; o >>= 1) mx = fmaxf(mx, __shfl_xor_sync(0xffffffffu, mx, o, 16));
        float sum = 0.f;
#pragma unroll
        for (int j = 0; j < 4; j++) { s[j] = __expf(s[j] - mx); sum += s[j]; }
        for (int o = 8; o; o >>= 1) sum += __shfl_xor_sync(0xffffffffu, sum, o, 16);
        const float inv = 1.0f / sum;
#pragma unroll
        for (int j = 0; j < 4; j++)
            outp[(ty * 4 + i) * 64 + tx * 4 + j] = s[j] * inv;
    }
}

// ---------------------------------------------------------------------------
// Kernel 3: fused flash attention (token path) + feature-attention apply.
// grid = (16 q-tiles, 96 bh). Q tile 64 rows, KV tiles 32 rows, online softmax.
// Afterwards: O[n,d] += sum_e vh[n,e] * f_attn[d,e]; writes t+f into g_tmp [B,N,C].
// ---------------------------------------------------------------------------
__global__ __launch_bounds__(256) void attn_kernel() {
    const int bh  = blockIdx.y;
    const int n0q = blockIdx.x * 64;
    const float* Qg = g_qh + (size_t)bh * NSEQ * NDH;
    const float* Kg = g_kh + (size_t)bh * NSEQ * NDH;
    const float* Vg = g_vh + (size_t)bh * NSEQ * NDH;

    __shared__ __align__(16) float smem[64 * 65 + 32 * 65 + 32 * 65 + 64 * 33];
    float* Qs = smem;                 // [64][65]
    float* Ks = smem + 64 * 65;       // [32][65]
    float* Vs = Ks + 32 * 65;         // [32][65]
    float* Ps = Vs + 32 * 65;         // [64][33]

    const int t = threadIdx.x, tx = t & 15, ty = t >> 4;

    // Load Q tile
#pragma unroll
    for (int u = 0; u < 4; u++) {
        const int f4 = t + u * 256;
        const int row = f4 >> 4, col = (f4 & 15) * 4;
        float4 v = *(const float4*)(Qg + (size_t)(n0q + row) * 64 + col);
        Qs[row * 65 + col + 0] = v.x; Qs[row * 65 + col + 1] = v.y;
        Qs[row * 65 + col + 2] = v.z; Qs[row * 65 + col + 3] = v.w;
    }

    float O[4][4] = {};
    float m_i[4], l_i[4];
#pragma unroll
    for (int i = 0; i < 4; i++) { m_i[i] = -INFINITY; l_i[i] = 0.f; }
    __syncthreads();

    for (int c0 = 0; c0 < NSEQ; c0 += 32) {
        // stage K,V tile into registers, then smem
        float4 kreg[2], vreg[2];
        int rw[2], cl[2];
#pragma unroll
        for (int u = 0; u < 2; u++) {
            const int f4 = t + u * 256;
            rw[u] = f4 >> 4; cl[u] = (f4 & 15) * 4;
            kreg[u] = *(const float4*)(Kg + (size_t)(c0 + rw[u]) * 64 + cl[u]);
            vreg[u] = *(const float4*)(Vg + (size_t)(c0 + rw[u]) * 64 + cl[u]);
        }
        __syncthreads();
#pragma unroll
        for (int u = 0; u < 2; u++) {
            Ks[rw[u] * 65 + cl[u] + 0] = kreg[u].x; Ks[rw[u] * 65 + cl[u] + 1] = kreg[u].y;
            Ks[rw[u] * 65 + cl[u] + 2] = kreg[u].z; Ks[rw[u] * 65 + cl[u] + 3] = kreg[u].w;
            Vs[rw[u] * 65 + cl[u] + 0] = vreg[u].x; Vs[rw[u] * 65 + cl[u] + 1] = vreg[u].y;
            Vs[rw[u] * 65 + cl[u] + 2] = vreg[u].z; Vs[rw[u] * 65 + cl[u] + 3] = vreg[u].w;
        }
        __syncthreads();

        // S = Q @ K^T : rows ty*4..+3, cols tx*2..+1
        float s0[4] = {}, s1[4] = {};
#pragma unroll 8
        for (int d = 0; d < 64; d++) {
            const float b0 = Ks[(tx * 2 + 0) * 65 + d];
            const float b1 = Ks[(tx * 2 + 1) * 65 + d];
#pragma unroll
            for (int i = 0; i < 4; i++) {
                const float a = Qs[(ty * 4 + i) * 65 + d];
                s0[i] += a * b0;
                s1[i] += a * b1;
            }
        }

        // online softmax update (rows split across 16 lanes with same ty)
#pragma unroll
        for (int i = 0; i < 4; i++) {
            float v0 = s0[i] * SCALE, v1 = s1[i] * SCALE;
            float mx = fmaxf(v0, v1);
            for (int o = 8; o; o >>= 1) mx = fmaxf(mx, __shfl_xor_sync(0xffffffffu, mx, o, 16));
            const float mnew = fmaxf(m_i[i], mx);
            const float corr = __expf(m_i[i] - mnew);
            const float p0 = __expf(v0 - mnew);
            const float p1 = __expf(v1 - mnew);
            float rs = p0 + p1;
            for (int o = 8; o; o >>= 1) rs += __shfl_xor_sync(0xffffffffu, rs, o, 16);
            l_i[i] = l_i[i] * corr + rs;
            m_i[i] = mnew;
#pragma unroll
            for (int u = 0; u < 4; u++) O[i][u] *= corr;
            Ps[(ty * 4 + i) * 33 + tx * 2 + 0] = p0;
            Ps[(ty * 4 + i) * 33 + tx * 2 + 1] = p1;
        }
        __syncthreads();

        // O += P @ V
#pragma unroll 8
        for (int c = 0; c < 32; c++) {
            float b[4];
#pragma unroll
            for (int u = 0; u < 4; u++) b[u] = Vs[c * 65 + tx * 4 + u];
#pragma unroll
            for (int i = 0; i < 4; i++) {
                const float a = Ps[(ty * 4 + i) * 33 + c];
#pragma unroll
                for (int u = 0; u < 4; u++) O[i][u] += a * b[u];
            }
        }
    }

    // normalize token-attention output
#pragma unroll
    for (int i = 0; i < 4; i++) {
        const float inv = 1.0f / l_i[i];
#pragma unroll
        for (int u = 0; u < 4; u++) O[i][u] *= inv;
    }

    // feature path: O[n,d] += sum_e vh[n,e] * f_attn[d,e]
    __syncthreads();
    float* Fa = Qs;   // [64][65]
    float* Vq = Ks;   // [64][65] spans Ks+Vs region
    const float* Fg = g_fattn + (size_t)bh * 4096;
#pragma unroll
    for (int u = 0; u < 4; u++) {
        const int f4 = t + u * 256;
        const int row = f4 >> 4, col = (f4 & 15) * 4;
        float4 fv = *(const float4*)(Fg + (size_t)row * 64 + col);
        float4 vv = *(const float4*)(Vg + (size_t)(n0q + row) * 64 + col);
        Fa[row * 65 + col + 0] = fv.x; Fa[row * 65 + col + 1] = fv.y;
        Fa[row * 65 + col + 2] = fv.z; Fa[row * 65 + col + 3] = fv.w;
        Vq[row * 65 + col + 0] = vv.x; Vq[row * 65 + col + 1] = vv.y;
        Vq[row * 65 + col + 2] = vv.z; Vq[row * 65 + col + 3] = vv.w;
    }
    __syncthreads();
#pragma unroll 8
    for (int e = 0; e < 64; e++) {
        float b[4];
#pragma unroll
        for (int u = 0; u < 4; u++) b[u] = Fa[(tx * 4 + u) * 65 + e];
#pragma unroll
        for (int i = 0; i < 4; i++) {
            const float a = Vq[(ty * 4 + i) * 65 + e];
#pragma unroll
            for (int u = 0; u < 4; u++) O[i][u] += a * b[u];
        }
    }

    // write t+f into [B,N,C]
    const int bb = bh / NH, h = bh - bb * NH;
#pragma unroll
    for (int i = 0; i < 4; i++) {
        const size_t row = (size_t)bb * NSEQ + n0q + ty * 4 + i;
#pragma unroll
        for (int u = 0; u < 4; u++)
            g_tmp[row * NC + h * 64 + tx * 4 + u] = O[i][u];
    }
}

// ---------------------------------------------------------------------------
// Kernel 4: output projection  out = (t+f) @ Wproj + bproj
// ---------------------------------------------------------------------------
__global__ __launch_bounds__(256) void proj_gemm(const float* __restrict__ W,
                                                 const float* __restrict__ bias,
                                                 float* __restrict__ out) {
    __shared__ __align__(16) float As[8 * 132];
    __shared__ __align__(16) float Bs[8 * 128];
    const int n0 = blockIdx.x * 128;
    const int m0 = blockIdx.y * 128;
    const int t  = threadIdx.x;
    const int tx = t & 15, ty = t >> 4;
    const int am = t >> 1,  ak = (t & 1) * 4;
    const int bk = t >> 5,  bn = (t & 31) * 4;

    float acc[8][8] = {};
    for (int k0 = 0; k0 < 768; k0 += 8) {
        float4 av = *(const float4*)(g_tmp + (size_t)(m0 + am) * 768 + k0 + ak);
        float4 bv = *(const float4*)(W + (size_t)(k0 + bk) * 768 + n0 + bn);
        __syncthreads();
        As[(ak + 0) * 132 + am] = av.x;
        As[(ak + 1) * 132 + am] = av.y;
        As[(ak + 2) * 132 + am] = av.z;
        As[(ak + 3) * 132 + am] = av.w;
        *(float4*)&Bs[bk * 128 + bn] = bv;
        __syncthreads();
#pragma unroll
        for (int kk = 0; kk < 8; kk++) {
            float a[8], b[8];
            *(float4*)&a[0] = *(const float4*)&As[kk * 132 + ty * 8];
            *(float4*)&a[4] = *(const float4*)&As[kk * 132 + ty * 8 + 4];
            *(float4*)&b[0] = *(const float4*)&Bs[kk * 128 + tx * 8];
            *(float4*)&b[4] = *(const float4*)&Bs[kk * 128 + tx * 8 + 4];
#pragma unroll
            for (int i = 0; i < 8; i++)
#pragma unroll
                for (int j = 0; j < 8; j++)
                    acc[i][j] += a[i] * b[j];
        }
    }

#pragma unroll
    for (int i = 0; i < 8; i++) {
        const size_t m = m0 + ty * 8 + i;
#pragma unroll
        for (int j = 0; j < 8; j++) {
            const int c = n0 + tx * 8 + j;
            out[m * 768 + c] = acc[i][j] + bias[c];
        }
    }
}

// ---------------------------------------------------------------------------
extern "C" void kernel_launch(void* const* d_in, const int* in_sizes, int n_in,
                              void* d_out, int out_size) {
    const float* q     = (const float*)d_in[0];
    const float* k     = (const float*)d_in[1];
    const float* Wq    = (const float*)d_in[2];
    const float* Wkv   = (const float*)d_in[3];
    const float* Wproj = (const float*)d_in[4];
    const float* bproj = (const float*)d_in[5];
    float* out = (float*)d_out;

    qkv_gemm<<<dim3(18, 64), 256>>>(q, k, Wq, Wkv);   // 2304/128 x 8192/128
    fattn_kernel<<<96, 256>>>();                      // one block per (b,h)
    attn_kernel<<<dim3(16, 96), 256>>>();             // q-tiles x (b,h)
    proj_gemm<<<dim3(6, 64), 256>>>(Wproj, bproj, out);
}

// round 3
// speedup vs baseline: 1.4333x; 1.4333x over previous
#include <cuda_runtime.h>
#include <math.h>

#define NB 8
#define NSEQ 1024
#define NC 768
#define NH 12
#define NDH 64
#define SCALE 0.125f

// Scratch device globals (no allocation allowed in kernel_launch)
__device__ float g_qh[NB * NH * NSEQ * NDH];     // [B,H,N,64]
__device__ float g_kh[NB * NH * NSEQ * NDH];
__device__ float g_vh[NB * NH * NSEQ * NDH];
__device__ float g_fattn[NB * NH * NDH * NDH];   // [B,H,64,64]
__device__ float g_tmp[NB * NSEQ * NC];          // t + f, [B,N,C]

__device__ __forceinline__ unsigned f2tf(float x) {
    unsigned r;
    asm("cvt.rna.tf32.f32 %0, %1;" : "=r"(r) : "f"(x));
    return r;
}

// Split x into tf32 hi + tf32 lo (x ≈ hi + lo to ~23 bits).
__device__ __forceinline__ void split(float x, unsigned& hi, unsigned& lo) {
    unsigned h = f2tf(x);
    hi = h;
    lo = f2tf(x - __uint_as_float(h));
}

// D += A(16x8) * B(8x8), tf32, fp32 accum.
__device__ __forceinline__ void mma8(float d[4], const unsigned a[4],
                                     unsigned b0, unsigned b1) {
    asm volatile(
        "mma.sync.aligned.m16n8k8.row.col.f32.tf32.tf32.f32 "
        "{%0,%1,%2,%3}, {%4,%5,%6,%7}, {%8,%9}, {%0,%1,%2,%3};"
        : "+f"(d[0]), "+f"(d[1]), "+f"(d[2]), "+f"(d[3])
        : "r"(a[0]), "r"(a[1]), "r"(a[2]), "r"(a[3]), "r"(b0), "r"(b1));
}

// 3xtf32: D += (Ahi+Alo)*(Bhi+Blo), dropping lo*lo.
__device__ __forceinline__ void mma3(float d[4],
                                     const unsigned ah[4], const unsigned al[4],
                                     unsigned bh0, unsigned bh1,
                                     unsigned bl0, unsigned bl1) {
    mma8(d, al, bh0, bh1);
    mma8(d, ah, bl0, bl1);
    mma8(d, ah, bh0, bh1);
}

// ---------------------------------------------------------------------------
// Kernel 1: fused QKV projection (3xtf32 tensor cores).
// C[8192,2304]: cols [0,768) = q@Wq -> g_qh ; cols [768,2304) = k@Wkv -> g_kh/g_vh
// Block 128x128, K-tile 32, 256 threads = 8 warps (4m x 2n), warp tile 32x64.
// ---------------------------------------------------------------------------
__global__ __launch_bounds__(256) void qkv_gemm(const float* __restrict__ q,
                                                const float* __restrict__ kx,
                                                const float* __restrict__ Wq,
                                                const float* __restrict__ Wkv) {
    __shared__ float As[128 * 36];   // [m][k] fp32, stride 36
    __shared__ float Bs[32 * 136];   // [k][n] fp32, stride 136

    const int n0 = blockIdx.x * 128;
    const int m0 = blockIdx.y * 128;
    const bool isQ = (n0 < 768);
    const float* A = isQ ? q : kx;
    const float* Bm;
    int ldb, cb;
    if (isQ) { Bm = Wq;  ldb = 768;  cb = n0; }
    else     { Bm = Wkv; ldb = 1536; cb = n0 - 768; }

    const int t = threadIdx.x, lane = t & 31, w = t >> 5;
    const int g = lane >> 2, tg = lane & 3;
    const int wm = w & 3, wn = w >> 2;
    const int ar = t >> 3, ac = (t & 7) * 4;
    const int br = t >> 3, bc = (t & 7) * 4;

    float acc[2][8][4] = {};
    float4 pa[4], pb[4];

#pragma unroll
    for (int u = 0; u < 4; u++) {
        pa[u] = *(const float4*)(A + (size_t)(m0 + ar + u * 32) * 768 + ac);
        pb[u] = *(const float4*)(Bm + (size_t)br * ldb + cb + bc + u * 32);
    }
#pragma unroll
    for (int u = 0; u < 4; u++) {
        *(float4*)&As[(ar + u * 32) * 36 + ac] = pa[u];
        *(float4*)&Bs[br * 136 + bc + u * 32] = pb[u];
    }
    __syncthreads();

    for (int k0 = 32; k0 <= 768; k0 += 32) {
        const bool more = (k0 < 768);
        if (more) {
#pragma unroll
            for (int u = 0; u < 4; u++) {
                pa[u] = *(const float4*)(A + (size_t)(m0 + ar + u * 32) * 768 + k0 + ac);
                pb[u] = *(const float4*)(Bm + (size_t)(k0 + br) * ldb + cb + bc + u * 32);
            }
        }
#pragma unroll
        for (int kk = 0; kk < 4; kk++) {
            const int k = kk * 8;
            unsigned ah[2][4], al[2][4];
#pragma unroll
            for (int i = 0; i < 2; i++) {
                const int rb = wm * 32 + i * 16 + g;
                split(As[rb * 36 + k + tg],           ah[i][0], al[i][0]);
                split(As[(rb + 8) * 36 + k + tg],     ah[i][1], al[i][1]);
                split(As[rb * 36 + k + tg + 4],       ah[i][2], al[i][2]);
                split(As[(rb + 8) * 36 + k + tg + 4], ah[i][3], al[i][3]);
            }
#pragma unroll
            for (int j = 0; j < 8; j++) {
                const int c = wn * 64 + j * 8 + g;
                unsigned bh0, bl0, bh1, bl1;
                split(Bs[(k + tg) * 136 + c],     bh0, bl0);
                split(Bs[(k + tg + 4) * 136 + c], bh1, bl1);
                mma3(acc[0][j], ah[0], al[0], bh0, bh1, bl0, bl1);
                mma3(acc[1][j], ah[1], al[1], bh0, bh1, bl0, bl1);
            }
        }
        if (more) {
            __syncthreads();
#pragma unroll
            for (int u = 0; u < 4; u++) {
                *(float4*)&As[(ar + u * 32) * 36 + ac] = pa[u];
                *(float4*)&Bs[br * 136 + bc + u * 32] = pb[u];
            }
            __syncthreads();
        }
    }

#pragma unroll
    for (int i = 0; i < 2; i++) {
        const int mA = m0 + wm * 32 + i * 16 + g;
#pragma unroll
        for (int half = 0; half < 2; half++) {
            const int m = mA + half * 8;
            const int bb = m >> 10, n = m & 1023;
#pragma unroll
            for (int j = 0; j < 8; j++) {
                const int cg = n0 + wn * 64 + j * 8 + tg * 2;
                float2 v = make_float2(acc[i][j][half * 2], acc[i][j][half * 2 + 1]);
                if (cg < 768) {
                    const int h = cg >> 6, d = cg & 63;
                    *(float2*)&g_qh[(((size_t)bb * NH + h) * NSEQ + n) * NDH + d] = v;
                } else {
                    const int cc = cg - 768;
                    const int c2 = (cc >= 768) ? cc - 768 : cc;
                    const int h = c2 >> 6, d = c2 & 63;
                    float* dst = (cc >= 768) ? g_vh : g_kh;
                    *(float2*)&dst[(((size_t)bb * NH + h) * NSEQ + n) * NDH + d] = v;
                }
            }
        }
    }
}

// ---------------------------------------------------------------------------
// Kernel 2: feature attention, 3xtf32. S[64,64] = Q^T K over N=1024.
// ---------------------------------------------------------------------------
__global__ __launch_bounds__(128) void fattn_kernel() {
    __shared__ float Qt[32 * 72];   // [n][d]
    __shared__ float Kt[32 * 72];
    __shared__ float Ss[64 * 65];
    __shared__ float sinv[64];

    const int bh = blockIdx.x;
    const float* Q = g_qh + (size_t)bh * NSEQ * NDH;
    const float* K = g_kh + (size_t)bh * NSEQ * NDH;

    const int t = threadIdx.x, lane = t & 31, w = t >> 5;
    const int g = lane >> 2, tg = lane & 3;
    const int lr = t >> 4, lc = (t & 15) * 4;

    float acc[8][4] = {};
    float4 pq[4], pk[4];

#pragma unroll
    for (int u = 0; u < 4; u++) {
        pq[u] = *(const float4*)(Q + (size_t)(lr + u * 8) * 64 + lc);
        pk[u] = *(const float4*)(K + (size_t)(lr + u * 8) * 64 + lc);
    }
#pragma unroll
    for (int u = 0; u < 4; u++) {
        *(float4*)&Qt[(lr + u * 8) * 72 + lc] = pq[u];
        *(float4*)&Kt[(lr + u * 8) * 72 + lc] = pk[u];
    }
    __syncthreads();

    for (int n0 = 32; n0 <= NSEQ; n0 += 32) {
        const bool more = (n0 < NSEQ);
        if (more) {
#pragma unroll
            for (int u = 0; u < 4; u++) {
                pq[u] = *(const float4*)(Q + (size_t)(n0 + lr + u * 8) * 64 + lc);
                pk[u] = *(const float4*)(K + (size_t)(n0 + lr + u * 8) * 64 + lc);
            }
        }
#pragma unroll
        for (int kk = 0; kk < 4; kk++) {
            const int k = kk * 8;
            const int mb = w * 16 + g;
            unsigned ah[4], al[4];
            split(Qt[(k + tg) * 72 + mb],         ah[0], al[0]);
            split(Qt[(k + tg) * 72 + mb + 8],     ah[1], al[1]);
            split(Qt[(k + tg + 4) * 72 + mb],     ah[2], al[2]);
            split(Qt[(k + tg + 4) * 72 + mb + 8], ah[3], al[3]);
#pragma unroll
            for (int j = 0; j < 8; j++) {
                const int c = j * 8 + g;
                unsigned bh0, bl0, bh1, bl1;
                split(Kt[(k + tg) * 72 + c],     bh0, bl0);
                split(Kt[(k + tg + 4) * 72 + c], bh1, bl1);
                mma3(acc[j], ah, al, bh0, bh1, bl0, bl1);
            }
        }
        if (more) {
            __syncthreads();
#pragma unroll
            for (int u = 0; u < 4; u++) {
                *(float4*)&Qt[(lr + u * 8) * 72 + lc] = pq[u];
                *(float4*)&Kt[(lr + u * 8) * 72 + lc] = pk[u];
            }
            __syncthreads();
        }
    }

#pragma unroll
    for (int j = 0; j < 8; j++) {
        const int r0 = w * 16 + g, c = j * 8 + tg * 2;
        Ss[r0 * 65 + c]           = acc[j][0] * SCALE;
        Ss[r0 * 65 + c + 1]       = acc[j][1] * SCALE;
        Ss[(r0 + 8) * 65 + c]     = acc[j][2] * SCALE;
        Ss[(r0 + 8) * 65 + c + 1] = acc[j][3] * SCALE;
    }
    __syncthreads();
    if (t < 64) {
        float mx = -INFINITY;
        for (int e = 0; e < 64; e++) mx = fmaxf(mx, Ss[t * 65 + e]);
        float s = 0.f;
        for (int e = 0; e < 64; e++) {
            float v = __expf(Ss[t * 65 + e] - mx);
            Ss[t * 65 + e] = v;
            s += v;
        }
        sinv[t] = 1.0f / s;
    }
    __syncthreads();
    float* outp = g_fattn + (size_t)bh * 4096;
    for (int idx = t; idx < 4096; idx += 128) {
        const int r = idx >> 6;
        outp[idx] = Ss[r * 65 + (idx & 63)] * sinv[r];
    }
}

// ---------------------------------------------------------------------------
// Kernel 3: flash attention (token path) + feature apply, 3xtf32.
// grid (16 qtiles, 96 bh), 128 threads = 4 warps (warp = 16 q-rows).
// ---------------------------------------------------------------------------
__global__ __launch_bounds__(128) void attn_kernel() {
    __shared__ float sm[11136];
    float* Qs = sm;             // [64][68]  (later Fa [d][e] stride 68)
    float* Ks = sm + 4352;      // [32][68]  (later Vq [64][68] spans K+V)
    float* Vs = sm + 6528;      // [32][72]
    float* Ps = sm + 8832;      // 4 warps x [16][36]

    const int bh = blockIdx.y;
    const int n0q = blockIdx.x * 64;
    const float* Qg = g_qh + (size_t)bh * NSEQ * NDH;
    const float* Kg = g_kh + (size_t)bh * NSEQ * NDH;
    const float* Vg = g_vh + (size_t)bh * NSEQ * NDH;

    const int t = threadIdx.x, lane = t & 31, w = t >> 5;
    const int g = lane >> 2, tg = lane & 3;
    const int lr = t >> 4, lc = (t & 15) * 4;

    // stage Q tile, hoist hi/lo fragments into registers
#pragma unroll
    for (int u = 0; u < 8; u++)
        *(float4*)&Qs[(lr + u * 8) * 68 + lc] =
            *(const float4*)(Qg + (size_t)(n0q + lr + u * 8) * 64 + lc);
    __syncthreads();
    unsigned qfh[8][4], qfl[8][4];
    {
        const int rb = w * 16 + g;
#pragma unroll
        for (int kk = 0; kk < 8; kk++) {
            const int k = kk * 8;
            split(Qs[rb * 68 + k + tg],           qfh[kk][0], qfl[kk][0]);
            split(Qs[(rb + 8) * 68 + k + tg],     qfh[kk][1], qfl[kk][1]);
            split(Qs[rb * 68 + k + tg + 4],       qfh[kk][2], qfl[kk][2]);
            split(Qs[(rb + 8) * 68 + k + tg + 4], qfh[kk][3], qfl[kk][3]);
        }
    }
    __syncthreads();

    float O[8][4] = {};
    float mr0 = -INFINITY, mr1 = -INFINITY, l0 = 0.f, l1 = 0.f;
    float* Pw = Ps + w * 16 * 36;

    float4 pk[4], pv[4];
#pragma unroll
    for (int u = 0; u < 4; u++) {
        pk[u] = *(const float4*)(Kg + (size_t)(lr + u * 8) * 64 + lc);
        pv[u] = *(const float4*)(Vg + (size_t)(lr + u * 8) * 64 + lc);
    }
#pragma unroll
    for (int u = 0; u < 4; u++) {
        *(float4*)&Ks[(lr + u * 8) * 68 + lc] = pk[u];
        *(float4*)&Vs[(lr + u * 8) * 72 + lc] = pv[u];
    }
    __syncthreads();

    for (int c0 = 32; c0 <= NSEQ; c0 += 32) {
        const bool more = (c0 < NSEQ);
        if (more) {
#pragma unroll
            for (int u = 0; u < 4; u++) {
                pk[u] = *(const float4*)(Kg + (size_t)(c0 + lr + u * 8) * 64 + lc);
                pv[u] = *(const float4*)(Vg + (size_t)(c0 + lr + u * 8) * 64 + lc);
            }
        }

        // S = Q K^T
        float sacc[4][4] = {};
#pragma unroll
        for (int kk = 0; kk < 8; kk++) {
            const int k = kk * 8;
#pragma unroll
            for (int j = 0; j < 4; j++) {
                const int c = j * 8 + g;
                unsigned bh0, bl0, bh1, bl1;
                split(Ks[c * 68 + k + tg],     bh0, bl0);
                split(Ks[c * 68 + k + tg + 4], bh1, bl1);
                mma3(sacc[j], qfh[kk], qfl[kk], bh0, bh1, bl0, bl1);
            }
        }

        // online softmax (rows g and g+8)
        float mx0 = -INFINITY, mx1 = -INFINITY;
#pragma unroll
        for (int j = 0; j < 4; j++) {
#pragma unroll
            for (int u = 0; u < 4; u++) sacc[j][u] *= SCALE;
            mx0 = fmaxf(mx0, fmaxf(sacc[j][0], sacc[j][1]));
            mx1 = fmaxf(mx1, fmaxf(sacc[j][2], sacc[j][3]));
        }
        mx0 = fmaxf(mx0, __shfl_xor_sync(0xffffffffu, mx0, 1));
        mx0 = fmaxf(mx0, __shfl_xor_sync(0xffffffffu, mx0, 2));
        mx1 = fmaxf(mx1, __shfl_xor_sync(0xffffffffu, mx1, 1));
        mx1 = fmaxf(mx1, __shfl_xor_sync(0xffffffffu, mx1, 2));
        const float mn0 = fmaxf(mr0, mx0), mn1 = fmaxf(mr1, mx1);
        const float co0 = __expf(mr0 - mn0), co1 = __expf(mr1 - mn1);
        float rs0 = 0.f, rs1 = 0.f;
#pragma unroll
        for (int j = 0; j < 4; j++) {
            const float p00 = __expf(sacc[j][0] - mn0);
            const float p01 = __expf(sacc[j][1] - mn0);
            const float p10 = __expf(sacc[j][2] - mn1);
            const float p11 = __expf(sacc[j][3] - mn1);
            rs0 += p00 + p01;
            rs1 += p10 + p11;
            const int c = j * 8 + tg * 2;
            Pw[g * 36 + c]           = p00;
            Pw[g * 36 + c + 1]       = p01;
            Pw[(g + 8) * 36 + c]     = p10;
            Pw[(g + 8) * 36 + c + 1] = p11;
        }
        rs0 += __shfl_xor_sync(0xffffffffu, rs0, 1);
        rs0 += __shfl_xor_sync(0xffffffffu, rs0, 2);
        rs1 += __shfl_xor_sync(0xffffffffu, rs1, 1);
        rs1 += __shfl_xor_sync(0xffffffffu, rs1, 2);
        l0 = l0 * co0 + rs0;
        l1 = l1 * co1 + rs1;
        mr0 = mn0;
        mr1 = mn1;
#pragma unroll
        for (int nt = 0; nt < 8; nt++) {
            O[nt][0] *= co0; O[nt][1] *= co0;
            O[nt][2] *= co1; O[nt][3] *= co1;
        }
        __syncwarp();

        // O += P @ V
#pragma unroll
        for (int kk = 0; kk < 4; kk++) {
            const int k = kk * 8;
            unsigned ah[4], al[4];
            split(Pw[g * 36 + k + tg],           ah[0], al[0]);
            split(Pw[(g + 8) * 36 + k + tg],     ah[1], al[1]);
            split(Pw[g * 36 + k + tg + 4],       ah[2], al[2]);
            split(Pw[(g + 8) * 36 + k + tg + 4], ah[3], al[3]);
#pragma unroll
            for (int nt = 0; nt < 8; nt++) {
                unsigned bh0, bl0, bh1, bl1;
                split(Vs[(k + tg) * 72 + nt * 8 + g],     bh0, bl0);
                split(Vs[(k + tg + 4) * 72 + nt * 8 + g], bh1, bl1);
                mma3(O[nt], ah, al, bh0, bh1, bl0, bl1);
            }
        }

        __syncthreads();
        if (more) {
#pragma unroll
            for (int u = 0; u < 4; u++) {
                *(float4*)&Ks[(lr + u * 8) * 68 + lc] = pk[u];
                *(float4*)&Vs[(lr + u * 8) * 72 + lc] = pv[u];
            }
            __syncthreads();
        }
    }

    // normalize token attention
    const float i0 = 1.0f / l0, i1 = 1.0f / l1;
#pragma unroll
    for (int nt = 0; nt < 8; nt++) {
        O[nt][0] *= i0; O[nt][1] *= i0;
        O[nt][2] *= i1; O[nt][3] *= i1;
    }

    // feature path: O[n,d] += sum_e V[n,e] * f_attn[d,e]
    float* Fa = Qs;   // [d][e] stride 68
    float* Vq = Ks;   // [r][e] stride 68
    const float* Fg = g_fattn + (size_t)bh * 4096;
#pragma unroll
    for (int u = 0; u < 8; u++) {
        const int row = lr + u * 8;
        *(float4*)&Fa[row * 68 + lc] = *(const float4*)(Fg + (size_t)row * 64 + lc);
        *(float4*)&Vq[row * 68 + lc] =
            *(const float4*)(Vg + (size_t)(n0q + row) * 64 + lc);
    }
    __syncthreads();
    {
        const int rb = w * 16 + g;
#pragma unroll
        for (int kk = 0; kk < 8; kk++) {
            const int k = kk * 8;
            unsigned ah[4], al[4];
            split(Vq[rb * 68 + k + tg],           ah[0], al[0]);
            split(Vq[(rb + 8) * 68 + k + tg],     ah[1], al[1]);
            split(Vq[rb * 68 + k + tg + 4],       ah[2], al[2]);
            split(Vq[(rb + 8) * 68 + k + tg + 4], ah[3], al[3]);
#pragma unroll
            for (int nt = 0; nt < 8; nt++) {
                unsigned bh0, bl0, bh1, bl1;
                split(Fa[(nt * 8 + g) * 68 + k + tg],     bh0, bl0);
                split(Fa[(nt * 8 + g) * 68 + k + tg + 4], bh1, bl1);
                mma3(O[nt], ah, al, bh0, bh1, bl0, bl1);
            }
        }
    }

    // store t+f into [B,N,C]
    const int bb = bh / NH, h = bh - bb * NH;
    const int r0 = n0q + w * 16 + g;
#pragma unroll
    for (int nt = 0; nt < 8; nt++) {
        const int col = h * 64 + nt * 8 + tg * 2;
        *(float2*)&g_tmp[((size_t)bb * NSEQ + r0) * NC + col] =
            make_float2(O[nt][0], O[nt][1]);
        *(float2*)&g_tmp[((size_t)bb * NSEQ + r0 + 8) * NC + col] =
            make_float2(O[nt][2], O[nt][3]);
    }
}

// ---------------------------------------------------------------------------
// Kernel 4: output projection, 3xtf32. out = (t+f) @ Wproj + bproj
// ---------------------------------------------------------------------------
__global__ __launch_bounds__(256) void proj_gemm(const float* __restrict__ W,
                                                 const float* __restrict__ bias,
                                                 float* __restrict__ out) {
    __shared__ float As[128 * 36];
    __shared__ float Bs[32 * 136];

    const int n0 = blockIdx.x * 128;
    const int m0 = blockIdx.y * 128;
    const int t = threadIdx.x, lane = t & 31, w = t >> 5;
    const int g = lane >> 2, tg = lane & 3;
    const int wm = w & 3, wn = w >> 2;
    const int ar = t >> 3, ac = (t & 7) * 4;
    const int br = t >> 3, bc = (t & 7) * 4;

    float acc[2][8][4] = {};
    float4 pa[4], pb[4];

#pragma unroll
    for (int u = 0; u < 4; u++) {
        pa[u] = *(const float4*)(g_tmp + (size_t)(m0 + ar + u * 32) * 768 + ac);
        pb[u] = *(const float4*)(W + (size_t)br * 768 + n0 + bc + u * 32);
    }
#pragma unroll
    for (int u = 0; u < 4; u++) {
        *(float4*)&As[(ar + u * 32) * 36 + ac] = pa[u];
        *(float4*)&Bs[br * 136 + bc + u * 32] = pb[u];
    }
    __syncthreads();

    for (int k0 = 32; k0 <= 768; k0 += 32) {
        const bool more = (k0 < 768);
        if (more) {
#pragma unroll
            for (int u = 0; u < 4; u++) {
                pa[u] = *(const float4*)(g_tmp + (size_t)(m0 + ar + u * 32) * 768 + k0 + ac);
                pb[u] = *(const float4*)(W + (size_t)(k0 + br) * 768 + n0 + bc + u * 32);
            }
        }
#pragma unroll
        for (int kk = 0; kk < 4; kk++) {
            const int k = kk * 8;
            unsigned ah[2][4], al[2][4];
#pragma unroll
            for (int i = 0; i < 2; i++) {
                const int rb = wm * 32 + i * 16 + g;
                split(As[rb * 36 + k + tg],           ah[i][0], al[i][0]);
                split(As[(rb + 8) * 36 + k + tg],     ah[i][1], al[i][1]);
                split(As[rb * 36 + k + tg + 4],       ah[i][2], al[i][2]);
                split(As[(rb + 8) * 36 + k + tg + 4], ah[i][3], al[i][3]);
            }
#pragma unroll
            for (int j = 0; j < 8; j++) {
                const int c = wn * 64 + j * 8 + g;
                unsigned bh0, bl0, bh1, bl1;
                split(Bs[(k + tg) * 136 + c],     bh0, bl0);
                split(Bs[(k + tg + 4) * 136 + c], bh1, bl1);
                mma3(acc[0][j], ah[0], al[0], bh0, bh1, bl0, bl1);
                mma3(acc[1][j], ah[1], al[1], bh0, bh1, bl0, bl1);
            }
        }
        if (more) {
            __syncthreads();
#pragma unroll
            for (int u = 0; u < 4; u++) {
                *(float4*)&As[(ar + u * 32) * 36 + ac] = pa[u];
                *(float4*)&Bs[br * 136 + bc + u * 32] = pb[u];
            }
            __syncthreads();
        }
    }

#pragma unroll
    for (int i = 0; i < 2; i++) {
        const int mA = m0 + wm * 32 + i * 16 + g;
#pragma unroll
        for (int half = 0; half < 2; half++) {
            const size_t m = mA + half * 8;
#pragma unroll
            for (int j = 0; j < 8; j++) {
                const int c = n0 + wn * 64 + j * 8 + tg * 2;
                float2 v = make_float2(acc[i][j][half * 2] + bias[c],
                                       acc[i][j][half * 2 + 1] + bias[c + 1]);
                *(float2*)&out[m * 768 + c] = v;
            }
        }
    }
}

// ---------------------------------------------------------------------------
extern "C" void kernel_launch(void* const* d_in, const int* in_sizes, int n_in,
                              void* d_out, int out_size) {
    const float* q     = (const float*)d_in[0];
    const float* k     = (const float*)d_in[1];
    const float* Wq    = (const float*)d_in[2];
    const float* Wkv   = (const float*)d_in[3];
    const float* Wproj = (const float*)d_in[4];
    const float* bproj = (const float*)d_in[5];
    float* out = (float*)d_out;

    qkv_gemm<<<dim3(18, 64), 256>>>(q, k, Wq, Wkv);
    fattn_kernel<<<96, 128>>>();
    attn_kernel<<<dim3(16, 96), 128>>>();
    proj_gemm<<<dim3(6, 64), 256>>>(Wproj, bproj, out);
}